// round 2
// baseline (speedup 1.0000x reference)
#include <cuda_runtime.h>
#include <cstdint>

// ---------------------------------------------------------------------------
// Toy MLP force kernel:  f = -d( sum(mlp(pos)) )/d(pos)
//   h1 = relu(pos @ W1^T + b1)   [N,8]
//   h2 = relu(h1 @ W2^T + b2)    [N,4]
//   out = h2 @ W3^T              [N,2], energy = sum(out)
// Backward collapses to: force = -W1^T * M1 * W2^T * (m2 .* g3),
// g3_j = W3[0][j] + W3[1][j] (constant). We precompute per-block in shared:
//   vtab[m2][k] = sum_j (m2_j active) g3_j * W2[j][k]   (16 x 8 floats, 512 B)
// Then per position only the forward pass + sign bits + 8 masked FMAs remain.
// ---------------------------------------------------------------------------

__device__ __forceinline__ unsigned prmt_(unsigned a, unsigned b, unsigned sel) {
    unsigned d;
    asm("prmt.b32 %0, %1, %2, %3;" : "=r"(d) : "r"(a), "r"(b), "r"(sel));
    return d;
}
__device__ __forceinline__ int dp4a_(unsigned a, unsigned b, int c) {
    int d;
    asm("dp4a.u32.u32 %0, %1, %2, %3;" : "=r"(d) : "r"(a), "r"(b), "r"(c));
    return d;
}

struct Wts {
    float w1x[8], w1y[8], bb1[8];   // W1[k][0], W1[k][1], b1[k]
    float w2[4][8];                  // W2[j][k]
    float bb2[4];                    // b2[j]
};

__device__ __forceinline__ float2 force_one(float x, float y, const Wts& W,
                                            const float4* __restrict__ vtab4) {
    // ---- forward layer 1 (keep pre-activation for the mask) ----
    float h1p[8], h1[8];
#pragma unroll
    for (int k = 0; k < 8; k++) {
        h1p[k] = fmaf(x, W.w1x[k], fmaf(y, W.w1y[k], W.bb1[k]));
        h1[k]  = fmaxf(h1p[k], 0.0f);
    }
    // ---- forward layer 2 (only sign needed) ----
    float h2p[4];
#pragma unroll
    for (int j = 0; j < 4; j++) {
        float s = W.bb2[j];
#pragma unroll
        for (int k = 0; k < 8; k++) s = fmaf(h1[k], W.w2[j][k], s);
        h2p[j] = s;
    }
    // ---- m2 index: bit j set iff h2p[j] < 0 (inactive) ----
    // PRMT sign-replicate gathers sign bytes; DP4A packs 4 bits in one op.
    unsigned s01 = prmt_(__float_as_uint(h2p[0]), __float_as_uint(h2p[1]), 0x00FBu);
    unsigned s23 = prmt_(__float_as_uint(h2p[2]), __float_as_uint(h2p[3]), 0x00FBu);
    unsigned m   = prmt_(s01, s23, 0x5410u) & 0x01010101u;
    int idx = dp4a_(m, 0x08040201u, 0);   // 0..15

    float4 va = vtab4[idx * 2 + 0];
    float4 vb = vtab4[idx * 2 + 1];
    float v[8] = {va.x, va.y, va.z, va.w, vb.x, vb.y, vb.z, vb.w};

    // ---- masked backward through layer 1: g1_k = (h1p_k > 0) ? v_k : 0 ----
    float fx = 0.0f, fy = 0.0f;
#pragma unroll
    for (int k = 0; k < 8; k++) {
        unsigned neg = (unsigned)(((int)__float_as_int(h1p[k])) >> 31); // 0xFFFFFFFF if negative
        float g = __uint_as_float(__float_as_uint(v[k]) & ~neg);
        fx = fmaf(g, W.w1x[k], fx);
        fy = fmaf(g, W.w1y[k], fy);
    }
    return make_float2(-fx, -fy);
}

__global__ __launch_bounds__(256)
void toy_force_kernel(const float4* __restrict__ pos4,
                      const float* __restrict__ W1,
                      const float* __restrict__ b1,
                      const float* __restrict__ W2,
                      const float* __restrict__ b2,
                      const float* __restrict__ W3,
                      float4* __restrict__ out4,
                      int n4) {
    __shared__ float4 vtab4[16 * 2];   // vtab[16][8] floats

    // Build the 16-entry backward LUT (one thread per (m2, k) pair).
    if (threadIdx.x < 128) {
        int m2 = threadIdx.x >> 3;
        int k  = threadIdx.x & 7;
        float s = 0.0f;
#pragma unroll
        for (int j = 0; j < 4; j++) {
            float g3 = W3[j] + W3[4 + j];           // colsum of W3 (2x4 row-major)
            if (!((m2 >> j) & 1)) s += g3 * W2[j * 8 + k];
        }
        reinterpret_cast<float*>(vtab4)[m2 * 8 + k] = s;
    }

    // Load all weights into registers (uniform -> L1 broadcast).
    Wts W;
#pragma unroll
    for (int k = 0; k < 8; k++) {
        W.w1x[k] = W1[k * 2 + 0];
        W.w1y[k] = W1[k * 2 + 1];
        W.bb1[k] = b1[k];
    }
#pragma unroll
    for (int j = 0; j < 4; j++) {
        W.bb2[j] = b2[j];
#pragma unroll
        for (int k = 0; k < 8; k++) W.w2[j][k] = W2[j * 8 + k];
    }
    __syncthreads();

    int tid = blockIdx.x * blockDim.x + threadIdx.x;
    int nthreads = gridDim.x * blockDim.x;
    for (int i = tid; i < n4; i += nthreads) {
        float4 p = __ldg(&pos4[i]);                 // two positions: (x,y),(z,w)
        float2 f0 = force_one(p.x, p.y, W, vtab4);
        float2 f1 = force_one(p.z, p.w, W, vtab4);
        out4[i] = make_float4(f0.x, f0.y, f1.x, f1.y);
    }
}

extern "C" void kernel_launch(void* const* d_in, const int* in_sizes, int n_in,
                              void* d_out, int out_size) {
    const float* pos = (const float*)d_in[0];   // [N,2] float32
    const float* W1  = (const float*)d_in[1];   // [8,2]
    const float* b1  = (const float*)d_in[2];   // [8]
    const float* W2  = (const float*)d_in[3];   // [4,8]
    const float* b2  = (const float*)d_in[4];   // [4]
    const float* W3  = (const float*)d_in[5];   // [2,4]
    float* out = (float*)d_out;                 // [N,2] float32

    int n4 = in_sizes[0] / 4;                   // float4s: 2 positions each
    const int threads = 256;
    int blocks = 1024;
    int needed = (n4 + threads - 1) / threads;
    if (needed < blocks) blocks = needed;

    toy_force_kernel<<<blocks, threads>>>(
        (const float4*)pos, W1, b1, W2, b2, W3, (float4*)out, n4);
}